// round 15
// baseline (speedup 1.0000x reference)
#include <cuda_runtime.h>
#include <cuda_bf16.h>

#define BB 16
#define SS 4096
#define DD 1024

#define GSPLIT 32      // split-K for the weight GEMVs
#define ESUM_TILES 64  // per-64-row-tile exp sums
#define CTX_TILES 32   // combined ctx partials (one per attn block pair)
#define QP_GRID  256
#define FIN_GRID 256

// ---------------- scratch (device globals; no allocations) ----------------
__device__ float g_q_part[GSPLIT][BB * DD];
__device__ float g_q[BB * DD];
__device__ float g_qk[BB * DD];
__device__ float g_esum_part[BB][ESUM_TILES];
__device__ float g_ctx_part[CTX_TILES][BB * DD];
__device__ float g_ctx[BB * DD];
__device__ float g_out_part[GSPLIT][BB * DD];
__device__ unsigned g_ctr[4];   // zero-initialized; restored to 0 on every exit

// ---------------------------------------------------------------------------
// Device-wide barrier. KEY FIX vs R14: poll with a volatile LOAD, not an
// atomic RMW — single-address atomics serialize at the LTS (~30 cyc/op), so
// 256 spinning pollers were costing ~4 us per barrier and starving the
// arriving atomicAdds. Loads are served concurrently.
// ---------------------------------------------------------------------------
template <int N>
__device__ __forceinline__ void grid_barrier(unsigned* c) {
    __syncthreads();
    if (threadIdx.x == 0) {
        __threadfence();
        atomicAdd(c, 1u);                               // arrive (one RMW)
        while (*(volatile unsigned*)c < (unsigned)N) { } // poll (loads only)
        __threadfence();
    }
    __syncthreads();
}

template <int N>
__device__ __forceinline__ void barrier_reset_exit() {
    __syncthreads();
    if (threadIdx.x == 0) {
        __threadfence();
        unsigned old = atomicAdd(&g_ctr[3], 1u);
        if (old == (unsigned)(N - 1)) {
            atomicExch(&g_ctr[0], 0u);
            atomicExch(&g_ctr[1], 0u);
            atomicExch(&g_ctr[2], 0u);
            atomicExch(&g_ctr[3], 0u);
        }
    }
}

// ---------------------------------------------------------------------------
// K1: QPROJ = gemv_part + reduce merged (R14, validated).
// grid 256, block 128.
// ---------------------------------------------------------------------------
__global__ void __launch_bounds__(128) qproj_kernel(const float* __restrict__ query,
                                                    const float* __restrict__ Wq) {
    __shared__ float xs[BB][DD / GSPLIT];   // 2 KB
    const int tid = threadIdx.x;
    const int bid = blockIdx.x;

    // ---- Phase 1: q partials. bid -> (hchunk = bid&7, split = bid>>3) ----
    {
        const int h  = (bid & 7) * 128 + tid;
        const int sp = bid >> 3;                  // 0..31
        const int i0 = sp * (DD / GSPLIT);

        for (int t = tid; t < BB * 32; t += 128) {
            int b = t >> 5, ii = t & 31;
            (&xs[0][0])[t] = query[b * DD + i0 + ii];
        }
        __syncthreads();

        float acc[BB];
#pragma unroll
        for (int b = 0; b < BB; b++) acc[b] = 0.f;
#pragma unroll 4
        for (int ii = 0; ii < 32; ii++) {
            float w = Wq[(size_t)(i0 + ii) * DD + h];
#pragma unroll
            for (int b = 0; b < BB; b++) acc[b] += xs[b][ii] * w;
        }
#pragma unroll
        for (int b = 0; b < BB; b++) g_q_part[sp][b * DD + h] = acc[b];
    }
    grid_barrier<QP_GRID>(&g_ctr[0]);

    // ---- Phase 2: reduce (guard: 32768 threads for 16384 elems) ----
    {
        const int idx = bid * 128 + tid;
        if (idx < BB * DD) {
            float s = 0.f;
#pragma unroll
            for (int k = 0; k < GSPLIT; k++) s += g_q_part[k][idx];
            g_q[idx] = s;
        }
    }
    barrier_reset_exit<QP_GRID>();
}

// ---------------------------------------------------------------------------
// K2: qk v2 (R13/R14, validated) — 2 rows per warp. grid 128, block 128.
// ---------------------------------------------------------------------------
__global__ void __launch_bounds__(128) qk_kernel(const float* __restrict__ Wk) {
    __shared__ __align__(16) float qs[BB][DD];   // 64 KB
    const int tid = threadIdx.x;

    for (int t = tid; t < BB * DD / 4; t += 128) {
        ((float4*)&qs[0][0])[t] = ((const float4*)g_q)[t];
    }
    __syncthreads();

    const int warp = tid >> 5;
    const int lane = tid & 31;
    const int r0 = blockIdx.x * 8 + warp * 2;
    const int r1 = r0 + 1;
    const float4* w0 = (const float4*)(Wk + (size_t)r0 * DD);
    const float4* w1 = (const float4*)(Wk + (size_t)r1 * DD);

    float acc0[BB], acc1[BB];
#pragma unroll
    for (int b = 0; b < BB; b++) { acc0[b] = 0.f; acc1[b] = 0.f; }

#pragma unroll
    for (int c = 0; c < DD / 4; c += 32) {
        float4 a4 = w0[c + lane];
        float4 b4 = w1[c + lane];
#pragma unroll
        for (int b = 0; b < BB; b++) {
            float4 q4 = ((const float4*)qs[b])[c + lane];
            acc0[b] += a4.x * q4.x + a4.y * q4.y + a4.z * q4.z + a4.w * q4.w;
            acc1[b] += b4.x * q4.x + b4.y * q4.y + b4.z * q4.z + b4.w * q4.w;
        }
    }
#pragma unroll
    for (int b = 0; b < BB; b++) {
        float v0 = acc0[b], v1 = acc1[b];
#pragma unroll
        for (int o = 16; o > 0; o >>= 1) {
            v0 += __shfl_down_sync(0xffffffffu, v0, o);
            v1 += __shfl_down_sync(0xffffffffu, v1, o);
        }
        if (lane == 0) {
            g_qk[b * DD + r0] = v0;
            g_qk[b * DD + r1] = v1;
        }
    }
}

// ---------------------------------------------------------------------------
// K3: fused attention (R14, validated): 2-tile blocks, combined ctx partial.
// grid 512, block 256.
// ---------------------------------------------------------------------------
__global__ void __launch_bounds__(256) attn_fused_kernel(const float* __restrict__ key,
                                                         const float* __restrict__ value) {
    const int b  = blockIdx.x >> 5;
    const int t0 = blockIdx.x & 31;
    const int warp = threadIdx.x >> 5;
    const int lane = threadIdx.x & 31;

    __shared__ __align__(16) float qk_s[DD];
    __shared__ float w_s[64];
    __shared__ float red[8];

    ((float4*)qk_s)[threadIdx.x] = ((const float4*)(g_qk + b * DD))[threadIdx.x];
    const float4* qrow = (const float4*)qk_s;

    float4 acc = make_float4(0.f, 0.f, 0.f, 0.f);   // persists across halves

#pragma unroll
    for (int half = 0; half < 2; half++) {
        const int tile = t0 + half * 32;
        const int s0 = tile * 64;
        __syncthreads();   // qk_s ready (h0) / w_s no longer read (h1)

        const float4* kbase = (const float4*)(key + ((size_t)b * SS + s0) * DD);

        // ---- Phase A: 2 groups of 4 rows per warp ----
        float esum = 0.f;
#pragma unroll
        for (int g = 0; g < 2; g++) {
            const int r = warp * 8 + g * 4;
            const float4* k0 = kbase + (size_t)(r + 0) * (DD / 4);
            const float4* k1 = kbase + (size_t)(r + 1) * (DD / 4);
            const float4* k2 = kbase + (size_t)(r + 2) * (DD / 4);
            const float4* k3 = kbase + (size_t)(r + 3) * (DD / 4);

            float a0 = 0.f, a1 = 0.f, a2 = 0.f, a3 = 0.f;
#pragma unroll
            for (int c = 0; c < DD / 4; c += 32) {
                float4 q4 = qrow[c + lane];
                float4 ka = __ldcs(&k0[c + lane]);
                float4 kb = __ldcs(&k1[c + lane]);
                float4 kc = __ldcs(&k2[c + lane]);
                float4 kd = __ldcs(&k3[c + lane]);
                a0 += ka.x * q4.x + ka.y * q4.y + ka.z * q4.z + ka.w * q4.w;
                a1 += kb.x * q4.x + kb.y * q4.y + kb.z * q4.z + kb.w * q4.w;
                a2 += kc.x * q4.x + kc.y * q4.y + kc.z * q4.z + kc.w * q4.w;
                a3 += kd.x * q4.x + kd.y * q4.y + kd.z * q4.z + kd.w * q4.w;
            }
#pragma unroll
            for (int o = 16; o > 0; o >>= 1) {
                a0 += __shfl_down_sync(0xffffffffu, a0, o);
                a1 += __shfl_down_sync(0xffffffffu, a1, o);
                a2 += __shfl_down_sync(0xffffffffu, a2, o);
                a3 += __shfl_down_sync(0xffffffffu, a3, o);
            }
            if (lane == 0) {
                float e0 = expf(a0 * 0.03125f);   // 1/sqrt(1024); bounded
                float e1 = expf(a1 * 0.03125f);
                float e2 = expf(a2 * 0.03125f);
                float e3 = expf(a3 * 0.03125f);
                w_s[r + 0] = e0; w_s[r + 1] = e1;
                w_s[r + 2] = e2; w_s[r + 3] = e3;
                esum += (e0 + e1) + (e2 + e3);
            }
        }
        if (lane == 0) red[warp] = esum;
        __syncthreads();

        if (threadIdx.x == 0) {
            float s = 0.f;
#pragma unroll
            for (int w = 0; w < 8; w++) s += red[w];
            g_esum_part[b][tile] = s;
        }

        // ---- Phase B: accumulate into persistent acc ----
        const float4* vbase = (const float4*)(value + ((size_t)b * SS + s0) * DD);
#pragma unroll 16
        for (int ss = 0; ss < 64; ss++) {
            float w = w_s[ss];
            float4 v = __ldcs(&vbase[(size_t)ss * (DD / 4) + threadIdx.x]);
            acc.x += w * v.x; acc.y += w * v.y; acc.z += w * v.z; acc.w += w * v.w;
        }
    }

    // single combined write (both tiles)
    ((float4*)g_ctx_part[t0])[b * (DD / 4) + threadIdx.x] = acc;
}

// ---------------------------------------------------------------------------
// K4: FINISH (R14 structure; barrier fix + phase-2 unroll 8).
// grid 256, block 128.
// ---------------------------------------------------------------------------
__global__ void __launch_bounds__(128) finish_kernel(const float* __restrict__ Wv,
                                                     float* __restrict__ out) {
    __shared__ float xs[BB][DD / GSPLIT];   // 2 KB
    const int tid = threadIdx.x;
    const int bid = blockIdx.x;

    // ---- Phase 1: normalize ctx (guard is load-bearing) ----
    {
        const int idx = bid * 128 + tid;
        if (idx < BB * DD) {
            const int b = idx >> 10;          // uniform within warp
            const int lane = tid & 31;
            float e = g_esum_part[b][lane] + g_esum_part[b][lane + 32];
#pragma unroll
            for (int o = 16; o > 0; o >>= 1) e += __shfl_down_sync(0xffffffffu, e, o);
            const float inv = 1.f / __shfl_sync(0xffffffffu, e, 0);

            float s = 0.f;
#pragma unroll
            for (int k = 0; k < CTX_TILES; k++) s += g_ctx_part[k][idx];
            g_ctx[idx] = s * inv;
        }
    }
    grid_barrier<FIN_GRID>(&g_ctr[0]);

    // ---- Phase 2: out partials. bid -> (hchunk = bid&7, split = bid>>3) ----
    {
        const int h  = (bid & 7) * 128 + tid;
        const int sp = bid >> 3;
        const int i0 = sp * (DD / GSPLIT);

        for (int t = tid; t < BB * 32; t += 128) {
            int b = t >> 5, ii = t & 31;
            (&xs[0][0])[t] = g_ctx[b * DD + i0 + ii];
        }
        __syncthreads();

        float acc[BB];
#pragma unroll
        for (int b = 0; b < BB; b++) acc[b] = 0.f;
#pragma unroll 8
        for (int ii = 0; ii < 32; ii++) {
            float w = Wv[(size_t)(i0 + ii) * DD + h];
#pragma unroll
            for (int b = 0; b < BB; b++) acc[b] += xs[b][ii] * w;
        }
#pragma unroll
        for (int b = 0; b < BB; b++) g_out_part[sp][b * DD + h] = acc[b];
    }
    grid_barrier<FIN_GRID>(&g_ctr[1]);

    // ---- Phase 3: reduce 32 partials -> d_out ----
    {
        const int idx = bid * 128 + tid;
        if (idx < BB * DD) {
            float s = 0.f;
#pragma unroll
            for (int k = 0; k < GSPLIT; k++) s += g_out_part[k][idx];
            out[idx] = s;
        }
    }
    barrier_reset_exit<FIN_GRID>();
}

// ---------------------------------------------------------------------------
extern "C" void kernel_launch(void* const* d_in, const int* in_sizes, int n_in,
                              void* d_out, int out_size) {
    const float* key   = (const float*)d_in[0];
    const float* query = (const float*)d_in[1];
    const float* value = (const float*)d_in[2];
    const float* Wk    = (const float*)d_in[3];
    const float* Wq    = (const float*)d_in[4];
    const float* Wv    = (const float*)d_in[5];
    float* out = (float*)d_out;

    // q = query @ Wq (gemv + reduce, one kernel)
    qproj_kernel<<<QP_GRID, 128>>>(query, Wq);
    // qk[b] = Wk @ q[b]
    qk_kernel<<<128, 128>>>(Wk);
    // fused attention (combined 2-tile ctx partials)
    attn_fused_kernel<<<512, 256>>>(key, value);
    // ctx normalize ; out = ctx@Wv ; out reduce
    finish_kernel<<<FIN_GRID, 128>>>(Wv, out);
}

// round 16
// speedup vs baseline: 1.0190x; 1.0190x over previous
#include <cuda_runtime.h>
#include <cuda_bf16.h>

#define BB 16
#define SS 4096
#define DD 1024

#define GSPLIT 32      // split-K for the weight GEMVs
#define ESUM_TILES 64  // per-64-row-tile exp sums
#define CTX_TILES 32   // combined ctx partials (one per attn block pair)

// ---------------- scratch (device globals; no allocations) ----------------
__device__ float g_q_part[GSPLIT][BB * DD];
__device__ float g_q[BB * DD];
__device__ float g_qk[BB * DD];
__device__ float g_esum_part[BB][ESUM_TILES];
__device__ float g_ctx_part[CTX_TILES][BB * DD];
__device__ float g_ctx[BB * DD];
__device__ float g_out_part[GSPLIT][BB * DD];

// ---------------------------------------------------------------------------
// K1/K6: split-K batched GEMV partials (R5/R13, validated).
// grid (8, 32) = 256 blocks, block 128.
// ---------------------------------------------------------------------------
__global__ void __launch_bounds__(128) gemv_part_kernel(const float* __restrict__ X,
                                                        const float* __restrict__ W,
                                                        float* __restrict__ part) {
    const int h  = blockIdx.x * 128 + threadIdx.x;
    const int IR = DD / GSPLIT;                     // 32
    const int i0 = blockIdx.y * IR;

    __shared__ float xs[BB][DD / GSPLIT];
    for (int t = threadIdx.x; t < BB * IR; t += 128) {
        int b = t >> 5, ii = t & 31;
        xs[b][ii] = X[b * DD + i0 + ii];
    }
    __syncthreads();

    float acc[BB];
#pragma unroll
    for (int b = 0; b < BB; b++) acc[b] = 0.f;

#pragma unroll 4
    for (int ii = 0; ii < IR; ii++) {
        float w = W[(size_t)(i0 + ii) * DD + h];
#pragma unroll
        for (int b = 0; b < BB; b++) acc[b] += xs[b][ii] * w;
    }

    float* p = part + (size_t)blockIdx.y * (BB * DD);
#pragma unroll
    for (int b = 0; b < BB; b++) p[b * DD + h] = acc[b];
}

// ---------------------------------------------------------------------------
// K2/K7: sum GSPLIT partials (R5/R13, validated). grid 128, block 128.
// ---------------------------------------------------------------------------
__global__ void __launch_bounds__(128) reduce32_kernel(const float* __restrict__ part,
                                                       float* __restrict__ out) {
    const int idx = blockIdx.x * 128 + threadIdx.x;
    float s = 0.f;
#pragma unroll
    for (int k = 0; k < GSPLIT; k++) s += part[(size_t)k * (BB * DD) + idx];
    out[idx] = s;
}

// ---------------------------------------------------------------------------
// K3: qk v2 (R13/R14, validated) — 2 rows per warp. grid 128, block 128.
// ---------------------------------------------------------------------------
__global__ void __launch_bounds__(128) qk_kernel(const float* __restrict__ Wk) {
    __shared__ __align__(16) float qs[BB][DD];   // 64 KB
    const int tid = threadIdx.x;

    for (int t = tid; t < BB * DD / 4; t += 128) {
        ((float4*)&qs[0][0])[t] = ((const float4*)g_q)[t];
    }
    __syncthreads();

    const int warp = tid >> 5;
    const int lane = tid & 31;
    const int r0 = blockIdx.x * 8 + warp * 2;
    const int r1 = r0 + 1;
    const float4* w0 = (const float4*)(Wk + (size_t)r0 * DD);
    const float4* w1 = (const float4*)(Wk + (size_t)r1 * DD);

    float acc0[BB], acc1[BB];
#pragma unroll
    for (int b = 0; b < BB; b++) { acc0[b] = 0.f; acc1[b] = 0.f; }

#pragma unroll
    for (int c = 0; c < DD / 4; c += 32) {
        float4 a4 = w0[c + lane];
        float4 b4 = w1[c + lane];
#pragma unroll
        for (int b = 0; b < BB; b++) {
            float4 q4 = ((const float4*)qs[b])[c + lane];
            acc0[b] += a4.x * q4.x + a4.y * q4.y + a4.z * q4.z + a4.w * q4.w;
            acc1[b] += b4.x * q4.x + b4.y * q4.y + b4.z * q4.z + b4.w * q4.w;
        }
    }
#pragma unroll
    for (int b = 0; b < BB; b++) {
        float v0 = acc0[b], v1 = acc1[b];
#pragma unroll
        for (int o = 16; o > 0; o >>= 1) {
            v0 += __shfl_down_sync(0xffffffffu, v0, o);
            v1 += __shfl_down_sync(0xffffffffu, v1, o);
        }
        if (lane == 0) {
            g_qk[b * DD + r0] = v0;
            g_qk[b * DD + r1] = v1;
        }
    }
}

// ---------------------------------------------------------------------------
// K4: fused attention (R14, validated): 2-tile blocks, combined ctx partial.
// grid 512, block 256.
// ---------------------------------------------------------------------------
__global__ void __launch_bounds__(256) attn_fused_kernel(const float* __restrict__ key,
                                                         const float* __restrict__ value) {
    const int b  = blockIdx.x >> 5;
    const int t0 = blockIdx.x & 31;
    const int warp = threadIdx.x >> 5;
    const int lane = threadIdx.x & 31;

    __shared__ __align__(16) float qk_s[DD];
    __shared__ float w_s[64];
    __shared__ float red[8];

    ((float4*)qk_s)[threadIdx.x] = ((const float4*)(g_qk + b * DD))[threadIdx.x];
    const float4* qrow = (const float4*)qk_s;

    float4 acc = make_float4(0.f, 0.f, 0.f, 0.f);   // persists across halves

#pragma unroll
    for (int half = 0; half < 2; half++) {
        const int tile = t0 + half * 32;
        const int s0 = tile * 64;
        __syncthreads();   // qk_s ready (h0) / w_s no longer read (h1)

        const float4* kbase = (const float4*)(key + ((size_t)b * SS + s0) * DD);

        // ---- Phase A: 2 groups of 4 rows per warp ----
        float esum = 0.f;
#pragma unroll
        for (int g = 0; g < 2; g++) {
            const int r = warp * 8 + g * 4;
            const float4* k0 = kbase + (size_t)(r + 0) * (DD / 4);
            const float4* k1 = kbase + (size_t)(r + 1) * (DD / 4);
            const float4* k2 = kbase + (size_t)(r + 2) * (DD / 4);
            const float4* k3 = kbase + (size_t)(r + 3) * (DD / 4);

            float a0 = 0.f, a1 = 0.f, a2 = 0.f, a3 = 0.f;
#pragma unroll
            for (int c = 0; c < DD / 4; c += 32) {
                float4 q4 = qrow[c + lane];
                float4 ka = __ldcs(&k0[c + lane]);
                float4 kb = __ldcs(&k1[c + lane]);
                float4 kc = __ldcs(&k2[c + lane]);
                float4 kd = __ldcs(&k3[c + lane]);
                a0 += ka.x * q4.x + ka.y * q4.y + ka.z * q4.z + ka.w * q4.w;
                a1 += kb.x * q4.x + kb.y * q4.y + kb.z * q4.z + kb.w * q4.w;
                a2 += kc.x * q4.x + kc.y * q4.y + kc.z * q4.z + kc.w * q4.w;
                a3 += kd.x * q4.x + kd.y * q4.y + kd.z * q4.z + kd.w * q4.w;
            }
#pragma unroll
            for (int o = 16; o > 0; o >>= 1) {
                a0 += __shfl_down_sync(0xffffffffu, a0, o);
                a1 += __shfl_down_sync(0xffffffffu, a1, o);
                a2 += __shfl_down_sync(0xffffffffu, a2, o);
                a3 += __shfl_down_sync(0xffffffffu, a3, o);
            }
            if (lane == 0) {
                float e0 = expf(a0 * 0.03125f);   // 1/sqrt(1024); bounded
                float e1 = expf(a1 * 0.03125f);
                float e2 = expf(a2 * 0.03125f);
                float e3 = expf(a3 * 0.03125f);
                w_s[r + 0] = e0; w_s[r + 1] = e1;
                w_s[r + 2] = e2; w_s[r + 3] = e3;
                esum += (e0 + e1) + (e2 + e3);
            }
        }
        if (lane == 0) red[warp] = esum;
        __syncthreads();

        if (threadIdx.x == 0) {
            float s = 0.f;
#pragma unroll
            for (int w = 0; w < 8; w++) s += red[w];
            g_esum_part[b][tile] = s;
        }

        // ---- Phase B: accumulate into persistent acc ----
        const float4* vbase = (const float4*)(value + ((size_t)b * SS + s0) * DD);
#pragma unroll 16
        for (int ss = 0; ss < 64; ss++) {
            float w = w_s[ss];
            float4 v = __ldcs(&vbase[(size_t)ss * (DD / 4) + threadIdx.x]);
            acc.x += w * v.x; acc.y += w * v.y; acc.z += w * v.z; acc.w += w * v.w;
        }
    }

    // single combined write (both tiles)
    ((float4*)g_ctx_part[t0])[b * (DD / 4) + threadIdx.x] = acc;
}

// ---------------------------------------------------------------------------
// K5: ctx normalize (finish phase-1 body, standalone; exact cover so no
// guard needed). grid 128, block 128.
// ---------------------------------------------------------------------------
__global__ void __launch_bounds__(128) norm_ctx_kernel() {
    const int tid = threadIdx.x;
    const int idx = blockIdx.x * 128 + tid;        // 128*128 = 16384 exact
    const int b = idx >> 10;                       // uniform within warp
    const int lane = tid & 31;

    float e = g_esum_part[b][lane] + g_esum_part[b][lane + 32];
#pragma unroll
    for (int o = 16; o > 0; o >>= 1) e += __shfl_down_sync(0xffffffffu, e, o);
    const float inv = 1.f / __shfl_sync(0xffffffffu, e, 0);

    float s = 0.f;
#pragma unroll
    for (int k = 0; k < CTX_TILES; k++) s += g_ctx_part[k][idx];
    g_ctx[idx] = s * inv;
}

// ---------------------------------------------------------------------------
extern "C" void kernel_launch(void* const* d_in, const int* in_sizes, int n_in,
                              void* d_out, int out_size) {
    const float* key   = (const float*)d_in[0];
    const float* query = (const float*)d_in[1];
    const float* value = (const float*)d_in[2];
    const float* Wk    = (const float*)d_in[3];
    const float* Wq    = (const float*)d_in[4];
    const float* Wv    = (const float*)d_in[5];
    float* out = (float*)d_out;

    float *d_q, *d_qpart, *d_ctx, *d_opart;
    cudaGetSymbolAddress((void**)&d_q, g_q);
    cudaGetSymbolAddress((void**)&d_qpart, g_q_part);
    cudaGetSymbolAddress((void**)&d_ctx, g_ctx);
    cudaGetSymbolAddress((void**)&d_opart, g_out_part);

    // q = query @ Wq
    gemv_part_kernel<<<dim3(DD / 128, GSPLIT), 128>>>(query, Wq, d_qpart);
    reduce32_kernel<<<BB * DD / 128, 128>>>(d_qpart, d_q);
    // qk[b] = Wk @ q[b]
    qk_kernel<<<128, 128>>>(Wk);
    // fused attention (combined 2-tile ctx partials)
    attn_fused_kernel<<<512, 256>>>(key, value);
    // ctx = (sum partials) / (sum exp)
    norm_ctx_kernel<<<128, 128>>>();
    // out = ctx @ Wv
    gemv_part_kernel<<<dim3(DD / 128, GSPLIT), 128>>>(d_ctx, Wv, d_opart);
    reduce32_kernel<<<BB * DD / 128, 128>>>(d_opart, out);
}